// round 10
// baseline (speedup 1.0000x reference)
#include <cuda_runtime.h>
#include <cuda_bf16.h>

// Problem constants
#define Bb 4
#define Ss 2048
#define Nn 2048
#define Dd 1024
#define Hh 16
#define HDd 64
static constexpr float EPS_ = 1e-5f;
static constexpr float QSCALE = 0.125f;   // HD^-0.5

// ---------------------------------------------------------------------------
// Scratch (device globals; no allocation allowed)
// ---------------------------------------------------------------------------
__device__ float g_kln[(size_t)Bb * Nn * HDd];        // 2 MB   : layernormed K
__device__ float g_att[(size_t)Bb * Ss * Dd];         // 32 MB  : attention out (B,S,D)
__device__ float g_xln[(size_t)Bb * Ss * Dd];         // 32 MB  : layernormed attention out

// ---------------------------------------------------------------------------
// Kernel 1: layernorm K rows (B*N rows of 64), warp per row
// ---------------------------------------------------------------------------
__global__ __launch_bounds__(256)
void kln_kernel(const float* __restrict__ xk,
                const float* __restrict__ w,
                const float* __restrict__ bi)
{
    int gw   = (blockIdx.x * blockDim.x + threadIdx.x) >> 5;   // global warp = row
    int lane = threadIdx.x & 31;
    if (gw >= Bb * Nn) return;
    const float* row = xk + (size_t)gw * HDd;
    float v0 = row[lane], v1 = row[lane + 32];
    float s = v0 + v1;
#pragma unroll
    for (int o = 16; o; o >>= 1) s += __shfl_xor_sync(0xffffffffu, s, o);
    float mean = s * (1.0f / HDd);
    float d0 = v0 - mean, d1 = v1 - mean;
    float vv = d0 * d0 + d1 * d1;
#pragma unroll
    for (int o = 16; o; o >>= 1) vv += __shfl_xor_sync(0xffffffffu, vv, o);
    float inv = rsqrtf(vv * (1.0f / HDd) + EPS_);
    float* orow = g_kln + (size_t)gw * HDd;
    orow[lane]      = d0 * inv * w[lane]      + bi[lane];
    orow[lane + 32] = d1 * inv * w[lane + 32] + bi[lane + 32];
}

// ---------------------------------------------------------------------------
// Kernel 2: flash attention.  Block = 64 query rows of one (b,h).
// 256 threads as 16x16; each thread owns a 4x4 microtile.
// Q layernorm+scale fused into the tile load.
// ---------------------------------------------------------------------------
__global__ __launch_bounds__(256)
void attn_kernel(const float* __restrict__ xq,
                 const float* __restrict__ xv,
                 const float* __restrict__ qw,
                 const float* __restrict__ qb)
{
    extern __shared__ float smem_[];
    float (*sQ)[68] = (float(*)[68])(smem_);
    float (*sK)[68] = (float(*)[68])(smem_ + 64 * 68);
    float (*sP)[68] = (float(*)[68])(smem_ + 2 * 64 * 68);
    float (*sV)[64] = (float(*)[64])(smem_ + 3 * 64 * 68);

    const int b  = blockIdx.z;
    const int h  = blockIdx.y;
    const int s0 = blockIdx.x * 64;
    const int tid = threadIdx.x;
    const int wid = tid >> 5, lane = tid & 31;
    const int ty = tid >> 4, tx = tid & 15;
    const int ty4 = ty * 4, tx4 = tx * 4;

    // --- Load Q tile with fused layernorm + scale (warp per row, 8 iters) ---
    {
        const size_t qbase = (size_t)b * (Ss * Dd) + (size_t)h * (Ss * HDd);
#pragma unroll
        for (int it = 0; it < 8; ++it) {
            int r = it * 8 + wid;
            const float* qr = xq + qbase + (size_t)(s0 + r) * HDd;
            float v0 = qr[lane], v1 = qr[lane + 32];
            float s = v0 + v1;
#pragma unroll
            for (int o = 16; o; o >>= 1) s += __shfl_xor_sync(0xffffffffu, s, o);
            float mean = s * (1.0f / HDd);
            float d0 = v0 - mean, d1 = v1 - mean;
            float vv = d0 * d0 + d1 * d1;
#pragma unroll
            for (int o = 16; o; o >>= 1) vv += __shfl_xor_sync(0xffffffffu, vv, o);
            float inv = rsqrtf(vv * (1.0f / HDd) + EPS_);
            sQ[r][lane]      = (d0 * inv * qw[lane]      + qb[lane])      * QSCALE;
            sQ[r][lane + 32] = (d1 * inv * qw[lane + 32] + qb[lane + 32]) * QSCALE;
        }
    }

    float m_i[4], l_i[4], o_acc[4][4];
#pragma unroll
    for (int r = 0; r < 4; ++r) {
        m_i[r] = -1e30f; l_i[r] = 0.0f;
#pragma unroll
        for (int c = 0; c < 4; ++c) o_acc[r][c] = 0.0f;
    }

    const size_t kvbase = (size_t)b * Nn * HDd;

    for (int t = 0; t < Nn / 64; ++t) {
        const int n0 = t * 64;
        __syncthreads();   // previous PV done; also covers Q-load on first iter

        // ---- load K (layernormed) and V tiles, fully coalesced float4 ----
        const size_t tbase = kvbase + (size_t)n0 * HDd;
#pragma unroll
        for (int i = 0; i < 4; ++i) {
            int lin = i * 256 + tid;
            int n  = lin >> 4;
            int d4 = (lin & 15) << 2;
            *(float4*)&sK[n][d4] = *(const float4*)(g_kln + tbase + (size_t)n * HDd + d4);
            *(float4*)&sV[n][d4] = *(const float4*)(xv    + tbase + (size_t)n * HDd + d4);
        }
        __syncthreads();

        // ---- S = Q K^T  (64x64x64) ----
        float acc[4][4];
#pragma unroll
        for (int r = 0; r < 4; ++r)
#pragma unroll
            for (int c = 0; c < 4; ++c) acc[r][c] = 0.0f;

#pragma unroll
        for (int kk = 0; kk < 64; kk += 4) {
            float4 a[4], bv[4];
#pragma unroll
            for (int r = 0; r < 4; ++r) a[r]  = *(const float4*)&sQ[ty4 + r][kk];
#pragma unroll
            for (int c = 0; c < 4; ++c) bv[c] = *(const float4*)&sK[tx4 + c][kk];
#pragma unroll
            for (int r = 0; r < 4; ++r)
#pragma unroll
                for (int c = 0; c < 4; ++c)
                    acc[r][c] += a[r].x * bv[c].x + a[r].y * bv[c].y
                               + a[r].z * bv[c].z + a[r].w * bv[c].w;
        }

        // ---- online softmax (row groups of 16 lanes) ----
#pragma unroll
        for (int r = 0; r < 4; ++r) {
            float tm = fmaxf(fmaxf(acc[r][0], acc[r][1]), fmaxf(acc[r][2], acc[r][3]));
#pragma unroll
            for (int o = 8; o; o >>= 1) tm = fmaxf(tm, __shfl_xor_sync(0xffffffffu, tm, o));
            float mn = fmaxf(m_i[r], tm);
            float corr = __expf(m_i[r] - mn);
            m_i[r] = mn;
            float rs = 0.0f;
#pragma unroll
            for (int c = 0; c < 4; ++c) {
                float p = __expf(acc[r][c] - mn);
                acc[r][c] = p;
                rs += p;
            }
#pragma unroll
            for (int o = 8; o; o >>= 1) rs += __shfl_xor_sync(0xffffffffu, rs, o);
            l_i[r] = l_i[r] * corr + rs;
#pragma unroll
            for (int c = 0; c < 4; ++c) o_acc[r][c] *= corr;
            *(float4*)&sP[ty4 + r][tx4] = make_float4(acc[r][0], acc[r][1], acc[r][2], acc[r][3]);
        }
        __syncthreads();

        // ---- O += P V  (64x64x64) ----
#pragma unroll
        for (int n = 0; n < 64; n += 4) {
            float4 p[4];
#pragma unroll
            for (int r = 0; r < 4; ++r) p[r] = *(const float4*)&sP[ty4 + r][n];
            float4 v0 = *(const float4*)&sV[n + 0][tx4];
            float4 v1 = *(const float4*)&sV[n + 1][tx4];
            float4 v2 = *(const float4*)&sV[n + 2][tx4];
            float4 v3 = *(const float4*)&sV[n + 3][tx4];
#pragma unroll
            for (int r = 0; r < 4; ++r) {
                o_acc[r][0] += p[r].x * v0.x + p[r].y * v1.x + p[r].z * v2.x + p[r].w * v3.x;
                o_acc[r][1] += p[r].x * v0.y + p[r].y * v1.y + p[r].z * v2.y + p[r].w * v3.y;
                o_acc[r][2] += p[r].x * v0.z + p[r].y * v1.z + p[r].z * v2.z + p[r].w * v3.z;
                o_acc[r][3] += p[r].x * v0.w + p[r].y * v1.w + p[r].z * v2.w + p[r].w * v3.w;
            }
        }
    }

    // ---- epilogue: normalize and scatter to (B, S, H, HD) layout ----
#pragma unroll
    for (int r = 0; r < 4; ++r) {
        float inv = 1.0f / l_i[r];
        float4 res = make_float4(o_acc[r][0] * inv, o_acc[r][1] * inv,
                                 o_acc[r][2] * inv, o_acc[r][3] * inv);
        size_t addr = (size_t)b * (Ss * Dd) + (size_t)(s0 + ty4 + r) * Dd + h * HDd + tx4;
        *(float4*)(g_att + addr) = res;
    }
}

// ---------------------------------------------------------------------------
// Kernel 3: layernorm over D=1024 (block per row, 256 threads, 1 float4 each)
// Cross-warp reduction fixed: guarded shuffle now uses an 8-lane mask (0xFF).
// A full 0xffffffff mask under `if (tid < 8)` deadlocks (lanes 8-31 never
// reach the shfl; lanes 0-7 wait forever) — this was the round-4 timeout.
// ---------------------------------------------------------------------------
__global__ __launch_bounds__(256)
void lnd_kernel(const float* __restrict__ w, const float* __restrict__ bi)
{
    __shared__ float sb[8];
    int row = blockIdx.x;
    int tid = threadIdx.x;
    int wid = tid >> 5, lane = tid & 31;

    float4 v = *(const float4*)(g_att + (size_t)row * Dd + tid * 4);

    float s = v.x + v.y + v.z + v.w;
#pragma unroll
    for (int o = 16; o; o >>= 1) s += __shfl_xor_sync(0xffffffffu, s, o);
    if (lane == 0) sb[wid] = s;
    __syncthreads();
    if (tid < 8) {
        float t = sb[tid];
#pragma unroll
        for (int o = 4; o; o >>= 1) t += __shfl_xor_sync(0xFFu, t, o);
        if (tid == 0) sb[0] = t;
    }
    __syncthreads();
    float mean = sb[0] * (1.0f / Dd);
    __syncthreads();

    float dx = v.x - mean, dy = v.y - mean, dz = v.z - mean, dw = v.w - mean;
    float vv = dx * dx + dy * dy + dz * dz + dw * dw;
#pragma unroll
    for (int o = 16; o; o >>= 1) vv += __shfl_xor_sync(0xffffffffu, vv, o);
    if (lane == 0) sb[wid] = vv;
    __syncthreads();
    if (tid < 8) {
        float t = sb[tid];
#pragma unroll
        for (int o = 4; o; o >>= 1) t += __shfl_xor_sync(0xFFu, t, o);
        if (tid == 0) sb[0] = t;
    }
    __syncthreads();
    float inv = rsqrtf(sb[0] * (1.0f / Dd) + EPS_);

    float4 w4 = *(const float4*)(w  + tid * 4);
    float4 b4 = *(const float4*)(bi + tid * 4);
    float4 r;
    r.x = dx * inv * w4.x + b4.x;
    r.y = dy * inv * w4.y + b4.y;
    r.z = dz * inv * w4.z + b4.z;
    r.w = dw * inv * w4.w + b4.w;
    *(float4*)(g_xln + (size_t)row * Dd + tid * 4) = r;
}

// ---------------------------------------------------------------------------
// Kernel 4: out = xln @ proj_w^T   (M=8192, N=1024, K=1024, both K-major "NT")
// 64x64 block tiles, BK=32, 4x4 per-thread microtiles.
// ---------------------------------------------------------------------------
__global__ __launch_bounds__(256)
void proj_kernel(const float* __restrict__ W, float* __restrict__ out)
{
    __shared__ float sXt[32][68];
    __shared__ float sWt[32][68];

    const int m0 = blockIdx.y * 64;
    const int n0 = blockIdx.x * 64;
    const int tid = threadIdx.x;
    const int ty4 = (tid >> 4) * 4, tx4 = (tid & 15) * 4;

    float acc[4][4];
#pragma unroll
    for (int r = 0; r < 4; ++r)
#pragma unroll
        for (int c = 0; c < 4; ++c) acc[r][c] = 0.0f;

    for (int kt = 0; kt < Dd; kt += 32) {
#pragma unroll
        for (int i = 0; i < 2; ++i) {
            int lin = i * 256 + tid;
            int row = lin >> 3;
            int k4  = (lin & 7) << 2;
            float4 xv = *(const float4*)(g_xln + (size_t)(m0 + row) * Dd + kt + k4);
            sXt[k4 + 0][row] = xv.x; sXt[k4 + 1][row] = xv.y;
            sXt[k4 + 2][row] = xv.z; sXt[k4 + 3][row] = xv.w;
            float4 wv = *(const float4*)(W + (size_t)(n0 + row) * Dd + kt + k4);
            sWt[k4 + 0][row] = wv.x; sWt[k4 + 1][row] = wv.y;
            sWt[k4 + 2][row] = wv.z; sWt[k4 + 3][row] = wv.w;
        }
        __syncthreads();
#pragma unroll
        for (int kk = 0; kk < 32; ++kk) {
            float4 a = *(const float4*)&sXt[kk][ty4];
            float4 b = *(const float4*)&sWt[kk][tx4];
            acc[0][0] += a.x * b.x; acc[0][1] += a.x * b.y; acc[0][2] += a.x * b.z; acc[0][3] += a.x * b.w;
            acc[1][0] += a.y * b.x; acc[1][1] += a.y * b.y; acc[1][2] += a.y * b.z; acc[1][3] += a.y * b.w;
            acc[2][0] += a.z * b.x; acc[2][1] += a.z * b.y; acc[2][2] += a.z * b.z; acc[2][3] += a.z * b.w;
            acc[3][0] += a.w * b.x; acc[3][1] += a.w * b.y; acc[3][2] += a.w * b.z; acc[3][3] += a.w * b.w;
        }
        __syncthreads();
    }

#pragma unroll
    for (int r = 0; r < 4; ++r) {
        float4 res = make_float4(acc[r][0], acc[r][1], acc[r][2], acc[r][3]);
        *(float4*)(out + (size_t)(m0 + ty4 + r) * Dd + n0 + tx4) = res;
    }
}

// ---------------------------------------------------------------------------
// Launch
// Inputs: 0 x_q, 1 x_k, 2 x_v, 3 qn_w, 4 qn_b, 5 kn_w, 6 kn_b, 7 n_w, 8 n_b, 9 proj_w
// ---------------------------------------------------------------------------
extern "C" void kernel_launch(void* const* d_in, const int* in_sizes, int n_in,
                              void* d_out, int out_size)
{
    const float* xq  = (const float*)d_in[0];
    const float* xk  = (const float*)d_in[1];
    const float* xv  = (const float*)d_in[2];
    const float* qnw = (const float*)d_in[3];
    const float* qnb = (const float*)d_in[4];
    const float* knw = (const float*)d_in[5];
    const float* knb = (const float*)d_in[6];
    const float* nw  = (const float*)d_in[7];
    const float* nb  = (const float*)d_in[8];
    const float* pw  = (const float*)d_in[9];
    float* out = (float*)d_out;

    // attn kernel needs 68608 B of dynamic smem (> 48KB default)
    cudaFuncSetAttribute(attn_kernel, cudaFuncAttributeMaxDynamicSharedMemorySize, 69632);

    // 1) layernorm K : 8192 rows, warp per row, 8 warps per block
    kln_kernel<<<(Bb * Nn) / 8, 256>>>(xk, knw, knb);

    // 2) flash attention : (S/64, H, B) blocks
    dim3 agrid(Ss / 64, Hh, Bb);
    attn_kernel<<<agrid, 256, 68608>>>(xq, xv, qnw, qnb);

    // 3) layernorm over D : one block per (b,s) row
    lnd_kernel<<<Bb * Ss, 256>>>(nw, nb);

    // 4) projection GEMM : (1024/64, 8192/64)
    dim3 pgrid(Dd / 64, (Bb * Ss) / 64);
    proj_kernel<<<pgrid, 256>>>(pw, out);
}

// round 11
// speedup vs baseline: 3.7901x; 3.7901x over previous
#include <cuda_runtime.h>
#include <cuda_bf16.h>
#include <cstdint>

// Problem constants
#define Bb 4
#define Ss 2048
#define Nn 2048
#define Dd 1024
#define Hh 16
#define HDd 64
static constexpr float EPS_ = 1e-5f;
static constexpr float QSCALE = 0.125f;   // HD^-0.5

// ---------------------------------------------------------------------------
// Scratch (device globals; no allocation allowed)
// ---------------------------------------------------------------------------
__device__ float g_kln[(size_t)Bb * Nn * HDd];        // 2 MB   : layernormed K
__device__ float g_att[(size_t)Bb * Ss * Dd];         // 32 MB  : attention out (B,S,D)
__device__ float g_xln[(size_t)Bb * Ss * Dd];         // 32 MB  : layernormed attention out

// ---------------------------------------------------------------------------
// tf32 helpers: split x into hi (tf32-rounded) + lo (tf32 of residual).
// 3-term MMA (hh + lh + hl) recovers ~fp32 accuracy on the tensor pipe.
// ---------------------------------------------------------------------------
__device__ __forceinline__ uint32_t f2tf(float x) {
    uint32_t r; asm("cvt.rna.tf32.f32 %0, %1;" : "=r"(r) : "f"(x)); return r;
}
__device__ __forceinline__ float2 split2(float x) {
    float h = __uint_as_float(f2tf(x));
    float l = __uint_as_float(f2tf(x - h));
    return make_float2(h, l);
}
__device__ __forceinline__ void split_store4(float4 v, float* ph, float* pl) {
    float2 a = split2(v.x), b = split2(v.y), c = split2(v.z), d = split2(v.w);
    *(float4*)ph = make_float4(a.x, b.x, c.x, d.x);
    *(float4*)pl = make_float4(a.y, b.y, c.y, d.y);
}
__device__ __forceinline__ void mma_tf32(float c[4],
                                         uint32_t a0, uint32_t a1, uint32_t a2, uint32_t a3,
                                         uint32_t b0, uint32_t b1) {
    asm volatile(
        "mma.sync.aligned.m16n8k8.row.col.f32.tf32.tf32.f32 "
        "{%0,%1,%2,%3}, {%4,%5,%6,%7}, {%8,%9}, {%0,%1,%2,%3};"
        : "+f"(c[0]), "+f"(c[1]), "+f"(c[2]), "+f"(c[3])
        : "r"(a0), "r"(a1), "r"(a2), "r"(a3), "r"(b0), "r"(b1));
}

// ---------------------------------------------------------------------------
// Kernel 1: layernorm K rows (B*N rows of 64), warp per row
// ---------------------------------------------------------------------------
__global__ __launch_bounds__(256)
void kln_kernel(const float* __restrict__ xk,
                const float* __restrict__ w,
                const float* __restrict__ bi)
{
    int gw   = (blockIdx.x * blockDim.x + threadIdx.x) >> 5;
    int lane = threadIdx.x & 31;
    if (gw >= Bb * Nn) return;
    const float* row = xk + (size_t)gw * HDd;
    float v0 = row[lane], v1 = row[lane + 32];
    float s = v0 + v1;
#pragma unroll
    for (int o = 16; o; o >>= 1) s += __shfl_xor_sync(0xffffffffu, s, o);
    float mean = s * (1.0f / HDd);
    float d0 = v0 - mean, d1 = v1 - mean;
    float vv = d0 * d0 + d1 * d1;
#pragma unroll
    for (int o = 16; o; o >>= 1) vv += __shfl_xor_sync(0xffffffffu, vv, o);
    float inv = rsqrtf(vv * (1.0f / HDd) + EPS_);
    float* orow = g_kln + (size_t)gw * HDd;
    orow[lane]      = d0 * inv * w[lane]      + bi[lane];
    orow[lane + 32] = d1 * inv * w[lane + 32] + bi[lane + 32];
}

// ---------------------------------------------------------------------------
// Kernel 2: tensor-core flash attention.
// Block = 128 query rows of one (b,h); 8 warps, each owning 16 rows x 64 cols.
// tf32 split (3 MMAs) for QK^T and PV; fp32 online softmax in C-fragments.
// Strides: 68 for row-major frag reads (banks gr*4+tc), 72 for V column reads
// (banks tc*8+gr) — both conflict-free.
// ---------------------------------------------------------------------------
#define QSTR 68
#define KSTR 68
#define VSTR 72

__global__ __launch_bounds__(256, 1)
void attn_tc_kernel(const float* __restrict__ xq, const float* __restrict__ xv,
                    const float* __restrict__ qw, const float* __restrict__ qb)
{
    extern __shared__ float sm[];
    float* sQh = sm;                    // 128*68
    float* sQl = sQh + 128 * QSTR;
    float* sPh = sQl + 128 * QSTR;      // 128*68
    float* sPl = sPh + 128 * QSTR;
    float* sKh = sPl + 128 * QSTR;      // 64*68
    float* sKl = sKh + 64 * KSTR;
    float* sVh = sKl + 64 * KSTR;       // 64*72
    float* sVl = sVh + 64 * VSTR;

    const int b  = blockIdx.z;
    const int h  = blockIdx.y;
    const int s0 = blockIdx.x * 128;
    const int tid = threadIdx.x, wid = tid >> 5, lane = tid & 31;
    const int gr = lane >> 2, tc = lane & 3;
    const int qr = wid * 16;            // warp's base row within tile

    // --- Q layernorm + scale, tf32-split into smem (warp per row, 16 iters) ---
    {
        const size_t qbase = (size_t)b * (Ss * Dd) + (size_t)h * (Ss * HDd);
#pragma unroll
        for (int it = 0; it < 16; ++it) {
            int r = it * 8 + wid;
            const float* qrow = xq + qbase + (size_t)(s0 + r) * HDd;
            float v0 = qrow[lane], v1 = qrow[lane + 32];
            float s = v0 + v1;
#pragma unroll
            for (int o = 16; o; o >>= 1) s += __shfl_xor_sync(0xffffffffu, s, o);
            float mean = s * (1.0f / HDd);
            float d0 = v0 - mean, d1 = v1 - mean;
            float vv = d0 * d0 + d1 * d1;
#pragma unroll
            for (int o = 16; o; o >>= 1) vv += __shfl_xor_sync(0xffffffffu, vv, o);
            float inv = rsqrtf(vv * (1.0f / HDd) + EPS_);
            float q0 = (d0 * inv * qw[lane]      + qb[lane])      * QSCALE;
            float q1 = (d1 * inv * qw[lane + 32] + qb[lane + 32]) * QSCALE;
            float2 h0 = split2(q0), h1 = split2(q1);
            sQh[r * QSTR + lane]      = h0.x; sQl[r * QSTR + lane]      = h0.y;
            sQh[r * QSTR + lane + 32] = h1.x; sQl[r * QSTR + lane + 32] = h1.y;
        }
    }

    float m0 = -1e30f, m1 = -1e30f, ls0 = 0.0f, ls1 = 0.0f;
    float oa[8][4];
#pragma unroll
    for (int j = 0; j < 8; ++j) { oa[j][0] = oa[j][1] = oa[j][2] = oa[j][3] = 0.0f; }

    const uint32_t* uQh = (const uint32_t*)sQh;
    const uint32_t* uQl = (const uint32_t*)sQl;
    const uint32_t* uPh = (const uint32_t*)sPh;
    const uint32_t* uPl = (const uint32_t*)sPl;
    const uint32_t* uKh = (const uint32_t*)sKh;
    const uint32_t* uKl = (const uint32_t*)sKl;
    const uint32_t* uVh = (const uint32_t*)sVh;
    const uint32_t* uVl = (const uint32_t*)sVl;

    const size_t kvbase = (size_t)b * Nn * HDd;

    for (int t = 0; t < Nn / 64; ++t) {
        __syncthreads();   // all warps done with previous tile's sK/sV (and P)

        // ---- load K (layernormed) and V tiles, split into tf32 hi/lo ----
        const size_t tb = kvbase + (size_t)t * 64 * HDd;
#pragma unroll
        for (int i = 0; i < 4; ++i) {
            int lin = i * 256 + tid;
            int n = lin >> 4, d4 = (lin & 15) << 2;
            float4 kv = *(const float4*)(g_kln + tb + (size_t)n * HDd + d4);
            float4 vv = *(const float4*)(xv    + tb + (size_t)n * HDd + d4);
            split_store4(kv, &sKh[n * KSTR + d4], &sKl[n * KSTR + d4]);
            split_store4(vv, &sVh[n * VSTR + d4], &sVl[n * VSTR + d4]);
        }
        __syncthreads();

        // ---- S = Q K^T : warp computes 16x64 via m16n8k8 tf32 (3-term) ----
        float sc[8][4];
#pragma unroll
        for (int j = 0; j < 8; ++j) { sc[j][0] = sc[j][1] = sc[j][2] = sc[j][3] = 0.0f; }
#pragma unroll
        for (int kk = 0; kk < 64; kk += 8) {
            int ab = (qr + gr) * QSTR + kk + tc;
            uint32_t ah0 = uQh[ab],     ah1 = uQh[ab + 8 * QSTR];
            uint32_t ah2 = uQh[ab + 4], ah3 = uQh[ab + 8 * QSTR + 4];
            uint32_t al0 = uQl[ab],     al1 = uQl[ab + 8 * QSTR];
            uint32_t al2 = uQl[ab + 4], al3 = uQl[ab + 8 * QSTR + 4];
#pragma unroll
            for (int j = 0; j < 8; ++j) {
                int bb = (j * 8 + gr) * KSTR + kk + tc;
                uint32_t bh0 = uKh[bb], bh1 = uKh[bb + 4];
                uint32_t bl0 = uKl[bb], bl1 = uKl[bb + 4];
                mma_tf32(sc[j], ah0, ah1, ah2, ah3, bh0, bh1);
                mma_tf32(sc[j], al0, al1, al2, al3, bh0, bh1);
                mma_tf32(sc[j], ah0, ah1, ah2, ah3, bl0, bl1);
            }
        }

        // ---- online softmax: lane owns rows (qr+gr) [c0,c1] and (qr+gr+8) [c2,c3] ----
        float tm0 = -1e30f, tm1 = -1e30f;
#pragma unroll
        for (int j = 0; j < 8; ++j) {
            tm0 = fmaxf(tm0, fmaxf(sc[j][0], sc[j][1]));
            tm1 = fmaxf(tm1, fmaxf(sc[j][2], sc[j][3]));
        }
        tm0 = fmaxf(tm0, __shfl_xor_sync(0xffffffffu, tm0, 1));
        tm0 = fmaxf(tm0, __shfl_xor_sync(0xffffffffu, tm0, 2));
        tm1 = fmaxf(tm1, __shfl_xor_sync(0xffffffffu, tm1, 1));
        tm1 = fmaxf(tm1, __shfl_xor_sync(0xffffffffu, tm1, 2));
        float mn0 = fmaxf(m0, tm0), mn1 = fmaxf(m1, tm1);
        float cr0 = __expf(m0 - mn0), cr1 = __expf(m1 - mn1);
        m0 = mn0; m1 = mn1;
        float rs0 = 0.0f, rs1 = 0.0f;
#pragma unroll
        for (int j = 0; j < 8; ++j) {
            float p00 = __expf(sc[j][0] - mn0), p01 = __expf(sc[j][1] - mn0);
            float p10 = __expf(sc[j][2] - mn1), p11 = __expf(sc[j][3] - mn1);
            rs0 += p00 + p01; rs1 += p10 + p11;
            oa[j][0] *= cr0; oa[j][1] *= cr0; oa[j][2] *= cr1; oa[j][3] *= cr1;
            float2 s00 = split2(p00), s01 = split2(p01);
            float2 s10 = split2(p10), s11 = split2(p11);
            int i0 = (qr + gr)     * QSTR + j * 8 + 2 * tc;
            int i1 = (qr + gr + 8) * QSTR + j * 8 + 2 * tc;
            *(float2*)&sPh[i0] = make_float2(s00.x, s01.x);
            *(float2*)&sPl[i0] = make_float2(s00.y, s01.y);
            *(float2*)&sPh[i1] = make_float2(s10.x, s11.x);
            *(float2*)&sPl[i1] = make_float2(s10.y, s11.y);
        }
        rs0 += __shfl_xor_sync(0xffffffffu, rs0, 1);
        rs0 += __shfl_xor_sync(0xffffffffu, rs0, 2);
        rs1 += __shfl_xor_sync(0xffffffffu, rs1, 1);
        rs1 += __shfl_xor_sync(0xffffffffu, rs1, 2);
        ls0 = ls0 * cr0 + rs0;
        ls1 = ls1 * cr1 + rs1;

        // P rows [qr, qr+16) are produced AND consumed by this warp only.
        __syncwarp();

        // ---- O += P V : A from sP (row-major), B from sV (column reads) ----
#pragma unroll
        for (int kk = 0; kk < 64; kk += 8) {
            int ab = (qr + gr) * QSTR + kk + tc;
            uint32_t ah0 = uPh[ab],     ah1 = uPh[ab + 8 * QSTR];
            uint32_t ah2 = uPh[ab + 4], ah3 = uPh[ab + 8 * QSTR + 4];
            uint32_t al0 = uPl[ab],     al1 = uPl[ab + 8 * QSTR];
            uint32_t al2 = uPl[ab + 4], al3 = uPl[ab + 8 * QSTR + 4];
#pragma unroll
            for (int j = 0; j < 8; ++j) {
                int bb = (kk + tc) * VSTR + j * 8 + gr;
                uint32_t bh0 = uVh[bb], bh1 = uVh[bb + 4 * VSTR];
                uint32_t bl0 = uVl[bb], bl1 = uVl[bb + 4 * VSTR];
                mma_tf32(oa[j], ah0, ah1, ah2, ah3, bh0, bh1);
                mma_tf32(oa[j], al0, al1, al2, al3, bh0, bh1);
                mma_tf32(oa[j], ah0, ah1, ah2, ah3, bl0, bl1);
            }
        }
    }

    // ---- epilogue: normalize, scatter to (B, S, H*HD) ----
    float i0 = 1.0f / ls0, i1 = 1.0f / ls1;
    size_t r0 = (size_t)b * (Ss * Dd) + (size_t)(s0 + qr + gr) * Dd + h * HDd;
    size_t r1 = r0 + (size_t)8 * Dd;
#pragma unroll
    for (int j = 0; j < 8; ++j) {
        *(float2*)(g_att + r0 + j * 8 + 2 * tc) = make_float2(oa[j][0] * i0, oa[j][1] * i0);
        *(float2*)(g_att + r1 + j * 8 + 2 * tc) = make_float2(oa[j][2] * i1, oa[j][3] * i1);
    }
}

// ---------------------------------------------------------------------------
// Kernel 3: layernorm over D=1024 (block per row, 256 threads, 1 float4 each)
// Guarded cross-warp shuffle uses an 8-lane mask (full-mask here deadlocks).
// ---------------------------------------------------------------------------
__global__ __launch_bounds__(256)
void lnd_kernel(const float* __restrict__ w, const float* __restrict__ bi)
{
    __shared__ float sb[8];
    int row = blockIdx.x;
    int tid = threadIdx.x;
    int wid = tid >> 5, lane = tid & 31;

    float4 v = *(const float4*)(g_att + (size_t)row * Dd + tid * 4);

    float s = v.x + v.y + v.z + v.w;
#pragma unroll
    for (int o = 16; o; o >>= 1) s += __shfl_xor_sync(0xffffffffu, s, o);
    if (lane == 0) sb[wid] = s;
    __syncthreads();
    if (tid < 8) {
        float t = sb[tid];
#pragma unroll
        for (int o = 4; o; o >>= 1) t += __shfl_xor_sync(0xFFu, t, o);
        if (tid == 0) sb[0] = t;
    }
    __syncthreads();
    float mean = sb[0] * (1.0f / Dd);
    __syncthreads();

    float dx = v.x - mean, dy = v.y - mean, dz = v.z - mean, dw = v.w - mean;
    float vv = dx * dx + dy * dy + dz * dz + dw * dw;
#pragma unroll
    for (int o = 16; o; o >>= 1) vv += __shfl_xor_sync(0xffffffffu, vv, o);
    if (lane == 0) sb[wid] = vv;
    __syncthreads();
    if (tid < 8) {
        float t = sb[tid];
#pragma unroll
        for (int o = 4; o; o >>= 1) t += __shfl_xor_sync(0xFFu, t, o);
        if (tid == 0) sb[0] = t;
    }
    __syncthreads();
    float inv = rsqrtf(sb[0] * (1.0f / Dd) + EPS_);

    float4 w4 = *(const float4*)(w  + tid * 4);
    float4 b4 = *(const float4*)(bi + tid * 4);
    float4 r;
    r.x = dx * inv * w4.x + b4.x;
    r.y = dy * inv * w4.y + b4.y;
    r.z = dz * inv * w4.z + b4.z;
    r.w = dw * inv * w4.w + b4.w;
    *(float4*)(g_xln + (size_t)row * Dd + tid * 4) = r;
}

// ---------------------------------------------------------------------------
// Kernel 4: out = xln @ proj_w^T via tf32 split MMAs.
// Block = 128(m) x 64(n), 8 warps x (16x64 warptile), BK=32.
// ---------------------------------------------------------------------------
#define XSTR 36

__global__ __launch_bounds__(256)
void proj_tc_kernel(const float* __restrict__ W, float* __restrict__ out)
{
    extern __shared__ float sm[];
    float* sXh = sm;                    // 128*36
    float* sXl = sXh + 128 * XSTR;
    float* sWh = sXl + 128 * XSTR;      // 64*36
    float* sWl = sWh + 64 * XSTR;

    const int m0 = blockIdx.y * 128;
    const int n0 = blockIdx.x * 64;
    const int tid = threadIdx.x, wid = tid >> 5, lane = tid & 31;
    const int gr = lane >> 2, tc = lane & 3;
    const int qr = wid * 16;

    const uint32_t* uXh = (const uint32_t*)sXh;
    const uint32_t* uXl = (const uint32_t*)sXl;
    const uint32_t* uWh = (const uint32_t*)sWh;
    const uint32_t* uWl = (const uint32_t*)sWl;

    float oa[8][4];
#pragma unroll
    for (int j = 0; j < 8; ++j) { oa[j][0] = oa[j][1] = oa[j][2] = oa[j][3] = 0.0f; }

    for (int kt = 0; kt < Dd; kt += 32) {
        __syncthreads();
#pragma unroll
        for (int i = 0; i < 4; ++i) {
            int lin = i * 256 + tid;
            int row = lin >> 3, c4 = (lin & 7) << 2;
            float4 xv = *(const float4*)(g_xln + (size_t)(m0 + row) * Dd + kt + c4);
            split_store4(xv, &sXh[row * XSTR + c4], &sXl[row * XSTR + c4]);
        }
#pragma unroll
        for (int i = 0; i < 2; ++i) {
            int lin = i * 256 + tid;
            int row = lin >> 3, c4 = (lin & 7) << 2;
            float4 wv = *(const float4*)(W + (size_t)(n0 + row) * Dd + kt + c4);
            split_store4(wv, &sWh[row * XSTR + c4], &sWl[row * XSTR + c4]);
        }
        __syncthreads();

#pragma unroll
        for (int kk = 0; kk < 32; kk += 8) {
            int ab = (qr + gr) * XSTR + kk + tc;
            uint32_t ah0 = uXh[ab],     ah1 = uXh[ab + 8 * XSTR];
            uint32_t ah2 = uXh[ab + 4], ah3 = uXh[ab + 8 * XSTR + 4];
            uint32_t al0 = uXl[ab],     al1 = uXl[ab + 8 * XSTR];
            uint32_t al2 = uXl[ab + 4], al3 = uXl[ab + 8 * XSTR + 4];
#pragma unroll
            for (int j = 0; j < 8; ++j) {
                int bb = (j * 8 + gr) * XSTR + kk + tc;
                uint32_t bh0 = uWh[bb], bh1 = uWh[bb + 4];
                uint32_t bl0 = uWl[bb], bl1 = uWl[bb + 4];
                mma_tf32(oa[j], ah0, ah1, ah2, ah3, bh0, bh1);
                mma_tf32(oa[j], al0, al1, al2, al3, bh0, bh1);
                mma_tf32(oa[j], ah0, ah1, ah2, ah3, bl0, bl1);
            }
        }
    }

    size_t r0 = (size_t)(m0 + qr + gr) * Dd + n0;
    size_t r1 = r0 + (size_t)8 * Dd;
#pragma unroll
    for (int j = 0; j < 8; ++j) {
        *(float2*)(out + r0 + j * 8 + 2 * tc) = make_float2(oa[j][0], oa[j][1]);
        *(float2*)(out + r1 + j * 8 + 2 * tc) = make_float2(oa[j][2], oa[j][3]);
    }
}

// ---------------------------------------------------------------------------
// Launch
// Inputs: 0 x_q, 1 x_k, 2 x_v, 3 qn_w, 4 qn_b, 5 kn_w, 6 kn_b, 7 n_w, 8 n_b, 9 proj_w
// ---------------------------------------------------------------------------
extern "C" void kernel_launch(void* const* d_in, const int* in_sizes, int n_in,
                              void* d_out, int out_size)
{
    const float* xq  = (const float*)d_in[0];
    const float* xk  = (const float*)d_in[1];
    const float* xv  = (const float*)d_in[2];
    const float* qnw = (const float*)d_in[3];
    const float* qnb = (const float*)d_in[4];
    const float* knw = (const float*)d_in[5];
    const float* knb = (const float*)d_in[6];
    const float* nw  = (const float*)d_in[7];
    const float* nb  = (const float*)d_in[8];
    const float* pw  = (const float*)d_in[9];
    float* out = (float*)d_out;

    // attention smem: (4*128*68 + 2*64*68 + 2*64*72) floats = 210944 bytes
    const int ATTN_SMEM = (4 * 128 * QSTR + 2 * 64 * KSTR + 2 * 64 * VSTR) * 4;
    const int PROJ_SMEM = (2 * 128 * XSTR + 2 * 64 * XSTR) * 4;   // 55296 bytes
    cudaFuncSetAttribute(attn_tc_kernel, cudaFuncAttributeMaxDynamicSharedMemorySize, ATTN_SMEM);
    cudaFuncSetAttribute(proj_tc_kernel, cudaFuncAttributeMaxDynamicSharedMemorySize, PROJ_SMEM);

    // 1) layernorm K : 8192 rows, warp per row, 8 warps per block
    kln_kernel<<<(Bb * Nn) / 8, 256>>>(xk, knw, knb);

    // 2) tensor-core flash attention : (S/128, H, B) blocks
    dim3 agrid(Ss / 128, Hh, Bb);
    attn_tc_kernel<<<agrid, 256, ATTN_SMEM>>>(xq, xv, qnw, qnb);

    // 3) layernorm over D : one block per (b,s) row
    lnd_kernel<<<Bb * Ss, 256>>>(nw, nb);

    // 4) projection GEMM : (N/64, M/128) blocks
    dim3 pgrid(Dd / 64, (Bb * Ss) / 128);
    proj_tc_kernel<<<pgrid, 256, PROJ_SMEM>>>(pw, out);
}

// round 12
// speedup vs baseline: 6.8454x; 1.8061x over previous
#include <cuda_runtime.h>
#include <cuda_bf16.h>
#include <cstdint>

// Problem constants
#define Bb 4
#define Ss 2048
#define Nn 2048
#define Dd 1024
#define Hh 16
#define HDd 64
static constexpr float EPS_ = 1e-5f;
static constexpr float QSCALE = 0.125f;   // HD^-0.5

// ---------------------------------------------------------------------------
// Scratch (device globals; no allocation allowed)
// ---------------------------------------------------------------------------
__device__ __nv_bfloat16 g_kh[(size_t)Bb * Nn * HDd];   // layernormed K, bf16 hi
__device__ __nv_bfloat16 g_kl[(size_t)Bb * Nn * HDd];   // layernormed K, bf16 lo
__device__ __nv_bfloat16 g_vh[(size_t)Bb * HDd * Nn];   // V transposed [b][d][n'], hi
__device__ __nv_bfloat16 g_vl[(size_t)Bb * HDd * Nn];   // V transposed, lo
__device__ __nv_bfloat16 g_wh[(size_t)Dd * Dd];         // proj W hi
__device__ __nv_bfloat16 g_wl[(size_t)Dd * Dd];         // proj W lo
__device__ float         g_att[(size_t)Bb * Ss * Dd];   // attention out (B,S,D) fp32
__device__ __nv_bfloat16 g_xh[(size_t)Bb * Ss * Dd];    // layernormed attn out hi
__device__ __nv_bfloat16 g_xl[(size_t)Bb * Ss * Dd];    // layernormed attn out lo

// ---------------------------------------------------------------------------
// helpers
// ---------------------------------------------------------------------------
__device__ __forceinline__ void bsplit(float x, __nv_bfloat16& h, __nv_bfloat16& l) {
    h = __float2bfloat16(x);
    l = __float2bfloat16(x - __bfloat162float(h));
}
__device__ __forceinline__ void mma_bf16(float c[4],
                                         uint32_t a0, uint32_t a1, uint32_t a2, uint32_t a3,
                                         uint32_t b0, uint32_t b1) {
    asm volatile(
        "mma.sync.aligned.m16n8k16.row.col.f32.bf16.bf16.f32 "
        "{%0,%1,%2,%3}, {%4,%5,%6,%7}, {%8,%9}, {%0,%1,%2,%3};"
        : "+f"(c[0]), "+f"(c[1]), "+f"(c[2]), "+f"(c[3])
        : "r"(a0), "r"(a1), "r"(a2), "r"(a3), "r"(b0), "r"(b1));
}
#define MMA3(C, AH0,AH1,AH2,AH3, AL0,AL1,AL2,AL3, BH0,BH1, BL0,BL1) \
    mma_bf16(C, AH0,AH1,AH2,AH3, BH0,BH1);                          \
    mma_bf16(C, AL0,AL1,AL2,AL3, BH0,BH1);                          \
    mma_bf16(C, AH0,AH1,AH2,AH3, BL0,BL1);

// ---------------------------------------------------------------------------
// Kernel 1: layernorm K rows (B*N rows of 64), warp per row, emit bf16 hi/lo
// ---------------------------------------------------------------------------
__global__ __launch_bounds__(256)
void kln_kernel(const float* __restrict__ xk,
                const float* __restrict__ w,
                const float* __restrict__ bi)
{
    int gw   = (blockIdx.x * blockDim.x + threadIdx.x) >> 5;
    int lane = threadIdx.x & 31;
    if (gw >= Bb * Nn) return;
    const float* row = xk + (size_t)gw * HDd;
    float v0 = row[lane], v1 = row[lane + 32];
    float s = v0 + v1;
#pragma unroll
    for (int o = 16; o; o >>= 1) s += __shfl_xor_sync(0xffffffffu, s, o);
    float mean = s * (1.0f / HDd);
    float d0 = v0 - mean, d1 = v1 - mean;
    float vv = d0 * d0 + d1 * d1;
#pragma unroll
    for (int o = 16; o; o >>= 1) vv += __shfl_xor_sync(0xffffffffu, vv, o);
    float inv = rsqrtf(vv * (1.0f / HDd) + EPS_);
    float o0 = d0 * inv * w[lane]      + bi[lane];
    float o1 = d1 * inv * w[lane + 32] + bi[lane + 32];
    __nv_bfloat16 h, l;
    size_t base = (size_t)gw * HDd;
    bsplit(o0, h, l); g_kh[base + lane]      = h; g_kl[base + lane]      = l;
    bsplit(o1, h, l); g_kh[base + lane + 32] = h; g_kl[base + lane + 32] = l;
}

// ---------------------------------------------------------------------------
// Kernel 1b: transpose + split V:  g_v{h,l}[b][d][n'] = split(xv[b][n'][d])
// Block handles one (b, 64-wide n' tile).
// ---------------------------------------------------------------------------
__global__ __launch_bounds__(256)
void vprep_kernel(const float* __restrict__ xv)
{
    __shared__ float tile[64][65];
    const int b = blockIdx.y;
    const int t = blockIdx.x;           // n' tile
    const int tid = threadIdx.x;
    const size_t src = (size_t)b * Nn * HDd + (size_t)t * 64 * HDd;
#pragma unroll
    for (int i = 0; i < 4; ++i) {
        int lin = i * 256 + tid;
        int r = lin >> 4, c4 = (lin & 15) * 4;
        float4 v = *(const float4*)(xv + src + (size_t)r * HDd + c4);
        tile[r][c4 + 0] = v.x; tile[r][c4 + 1] = v.y;
        tile[r][c4 + 2] = v.z; tile[r][c4 + 3] = v.w;
    }
    __syncthreads();
    const int d = tid >> 2, g = tid & 3;
    size_t dst = ((size_t)b * HDd + d) * Nn + (size_t)t * 64 + g * 16;
#pragma unroll
    for (int i = 0; i < 16; ++i) {
        __nv_bfloat16 h, l;
        bsplit(tile[g * 16 + i][d], h, l);
        g_vh[dst + i] = h; g_vl[dst + i] = l;
    }
}

// ---------------------------------------------------------------------------
// Kernel 1c: split proj W into bf16 hi/lo
// ---------------------------------------------------------------------------
__global__ __launch_bounds__(256)
void wprep_kernel(const float* __restrict__ W)
{
    size_t g = (size_t)blockIdx.x * 256 + threadIdx.x;   // float4 index
    float4 v = ((const float4*)W)[g];
    __nv_bfloat16 h0,l0,h1,l1,h2,l2,h3,l3;
    bsplit(v.x,h0,l0); bsplit(v.y,h1,l1); bsplit(v.z,h2,l2); bsplit(v.w,h3,l3);
    __nv_bfloat162* ph = (__nv_bfloat162*)(g_wh + g * 4);
    __nv_bfloat162* pl = (__nv_bfloat162*)(g_wl + g * 4);
    ph[0] = __nv_bfloat162(h0, h1); ph[1] = __nv_bfloat162(h2, h3);
    pl[0] = __nv_bfloat162(l0, l1); pl[1] = __nv_bfloat162(l2, l3);
}

// ---------------------------------------------------------------------------
// Kernel 2: bf16 tensor-core flash attention (3-term split).
// Block = 128 query rows of one (b,h); 8 warps x (16 x 64) warptiles.
// smem strides: 72 bf16 (144 B) -> conflict-free fragment access.
// ---------------------------------------------------------------------------
#define BSTR 72              // bf16 elements per smem row
#define USTR 36              // uint32 (bf16x2) per smem row

__global__ __launch_bounds__(256, 2)
void attn_tc_kernel(const float* __restrict__ xq,
                    const float* __restrict__ qw, const float* __restrict__ qb)
{
    extern __shared__ __nv_bfloat16 sb[];
    __nv_bfloat16* sQh = sb;                    // 128*72
    __nv_bfloat16* sQl = sQh + 128 * BSTR;
    __nv_bfloat16* sPh = sQl + 128 * BSTR;      // 128*72
    __nv_bfloat16* sPl = sPh + 128 * BSTR;
    __nv_bfloat16* sKh = sPl + 128 * BSTR;      // 64*72
    __nv_bfloat16* sKl = sKh + 64 * BSTR;
    __nv_bfloat16* sVh = sKl + 64 * BSTR;       // 64*72  (rows = d, cols = n')
    __nv_bfloat16* sVl = sVh + 64 * BSTR;

    const int b  = blockIdx.z;
    const int h  = blockIdx.y;
    const int s0 = blockIdx.x * 128;
    const int tid = threadIdx.x, wid = tid >> 5, lane = tid & 31;
    const int gr = lane >> 2, tc = lane & 3;
    const int qr = wid * 16;

    // --- Q layernorm + scale, bf16-split into smem ---
    {
        const size_t qbase = (size_t)b * (Ss * Dd) + (size_t)h * (Ss * HDd);
#pragma unroll
        for (int it = 0; it < 16; ++it) {
            int r = it * 8 + wid;
            const float* qrow = xq + qbase + (size_t)(s0 + r) * HDd;
            float v0 = qrow[lane], v1 = qrow[lane + 32];
            float s = v0 + v1;
#pragma unroll
            for (int o = 16; o; o >>= 1) s += __shfl_xor_sync(0xffffffffu, s, o);
            float mean = s * (1.0f / HDd);
            float d0 = v0 - mean, d1 = v1 - mean;
            float vv = d0 * d0 + d1 * d1;
#pragma unroll
            for (int o = 16; o; o >>= 1) vv += __shfl_xor_sync(0xffffffffu, vv, o);
            float inv = rsqrtf(vv * (1.0f / HDd) + EPS_);
            float q0 = (d0 * inv * qw[lane]      + qb[lane])      * QSCALE;
            float q1 = (d1 * inv * qw[lane + 32] + qb[lane + 32]) * QSCALE;
            __nv_bfloat16 hh, ll;
            bsplit(q0, hh, ll); sQh[r * BSTR + lane]      = hh; sQl[r * BSTR + lane]      = ll;
            bsplit(q1, hh, ll); sQh[r * BSTR + lane + 32] = hh; sQl[r * BSTR + lane + 32] = ll;
        }
    }

    float m0 = -1e30f, m1 = -1e30f, ls0 = 0.0f, ls1 = 0.0f;
    float oa[8][4];
#pragma unroll
    for (int j = 0; j < 8; ++j) { oa[j][0] = oa[j][1] = oa[j][2] = oa[j][3] = 0.0f; }

    const uint32_t* uQh = (const uint32_t*)sQh;
    const uint32_t* uQl = (const uint32_t*)sQl;
    uint32_t* uPh = (uint32_t*)sPh;
    uint32_t* uPl = (uint32_t*)sPl;
    const uint32_t* uKh = (const uint32_t*)sKh;
    const uint32_t* uKl = (const uint32_t*)sKl;
    const uint32_t* uVh = (const uint32_t*)sVh;
    const uint32_t* uVl = (const uint32_t*)sVl;

    const size_t kbase = (size_t)b * Nn * HDd;    // g_k layout [b][n'][d]
    const size_t vbase = (size_t)b * HDd * Nn;    // g_v layout [b][d][n']

    for (int t = 0; t < Nn / 64; ++t) {
        __syncthreads();   // all warps done with previous tile's sK/sV

        // ---- fill K (hi/lo) and V (hi/lo, transposed) tiles: uint4 copies ----
        {
            const size_t kt = kbase + (size_t)t * 64 * HDd;
            const size_t vt = vbase + (size_t)t * 64;
#pragma unroll
            for (int i = 0; i < 2; ++i) {
                int idx = i * 256 + tid;
                int row = idx >> 3, c8 = (idx & 7) * 8;
                *(uint4*)&sKh[row * BSTR + c8] = *(const uint4*)(g_kh + kt + (size_t)row * HDd + c8);
                *(uint4*)&sKl[row * BSTR + c8] = *(const uint4*)(g_kl + kt + (size_t)row * HDd + c8);
                *(uint4*)&sVh[row * BSTR + c8] = *(const uint4*)(g_vh + vt + (size_t)row * Nn + c8);
                *(uint4*)&sVl[row * BSTR + c8] = *(const uint4*)(g_vl + vt + (size_t)row * Nn + c8);
            }
        }
        __syncthreads();

        // ---- S = Q K^T : 4 k16-steps, 3-term bf16 ----
        float sc[8][4];
#pragma unroll
        for (int j = 0; j < 8; ++j) { sc[j][0] = sc[j][1] = sc[j][2] = sc[j][3] = 0.0f; }
#pragma unroll
        for (int kh = 0; kh < 32; kh += 8) {       // kh = k/2 (uint32 units)
            int a0i = (qr + gr) * USTR + kh + tc;
            int a1i = a0i + 8 * USTR;
            uint32_t ah0 = uQh[a0i], ah1 = uQh[a1i], ah2 = uQh[a0i + 4], ah3 = uQh[a1i + 4];
            uint32_t al0 = uQl[a0i], al1 = uQl[a1i], al2 = uQl[a0i + 4], al3 = uQl[a1i + 4];
#pragma unroll
            for (int j = 0; j < 8; ++j) {
                int bi = (j * 8 + gr) * USTR + kh + tc;
                uint32_t bh0 = uKh[bi], bh1 = uKh[bi + 4];
                uint32_t bl0 = uKl[bi], bl1 = uKl[bi + 4];
                MMA3(sc[j], ah0,ah1,ah2,ah3, al0,al1,al2,al3, bh0,bh1, bl0,bl1);
            }
        }

        // ---- online softmax; write P (bf16 hi/lo) ----
        float tm0 = -1e30f, tm1 = -1e30f;
#pragma unroll
        for (int j = 0; j < 8; ++j) {
            tm0 = fmaxf(tm0, fmaxf(sc[j][0], sc[j][1]));
            tm1 = fmaxf(tm1, fmaxf(sc[j][2], sc[j][3]));
        }
        tm0 = fmaxf(tm0, __shfl_xor_sync(0xffffffffu, tm0, 1));
        tm0 = fmaxf(tm0, __shfl_xor_sync(0xffffffffu, tm0, 2));
        tm1 = fmaxf(tm1, __shfl_xor_sync(0xffffffffu, tm1, 1));
        tm1 = fmaxf(tm1, __shfl_xor_sync(0xffffffffu, tm1, 2));
        float mn0 = fmaxf(m0, tm0), mn1 = fmaxf(m1, tm1);
        float cr0 = __expf(m0 - mn0), cr1 = __expf(m1 - mn1);
        m0 = mn0; m1 = mn1;
        float rs0 = 0.0f, rs1 = 0.0f;
#pragma unroll
        for (int j = 0; j < 8; ++j) {
            float p00 = __expf(sc[j][0] - mn0), p01 = __expf(sc[j][1] - mn0);
            float p10 = __expf(sc[j][2] - mn1), p11 = __expf(sc[j][3] - mn1);
            rs0 += p00 + p01; rs1 += p10 + p11;
            oa[j][0] *= cr0; oa[j][1] *= cr0; oa[j][2] *= cr1; oa[j][3] *= cr1;
            __nv_bfloat162 hp0 = __floats2bfloat162_rn(p00, p01);
            float2 hf0 = __bfloat1622float2(hp0);
            __nv_bfloat162 lp0 = __floats2bfloat162_rn(p00 - hf0.x, p01 - hf0.y);
            __nv_bfloat162 hp1 = __floats2bfloat162_rn(p10, p11);
            float2 hf1 = __bfloat1622float2(hp1);
            __nv_bfloat162 lp1 = __floats2bfloat162_rn(p10 - hf1.x, p11 - hf1.y);
            int i0 = (qr + gr)     * USTR + j * 4 + tc;
            int i1 = (qr + gr + 8) * USTR + j * 4 + tc;
            uPh[i0] = *(uint32_t*)&hp0; uPl[i0] = *(uint32_t*)&lp0;
            uPh[i1] = *(uint32_t*)&hp1; uPl[i1] = *(uint32_t*)&lp1;
        }
        rs0 += __shfl_xor_sync(0xffffffffu, rs0, 1);
        rs0 += __shfl_xor_sync(0xffffffffu, rs0, 2);
        rs1 += __shfl_xor_sync(0xffffffffu, rs1, 1);
        rs1 += __shfl_xor_sync(0xffffffffu, rs1, 2);
        ls0 = ls0 * cr0 + rs0;
        ls1 = ls1 * cr1 + rs1;

        __syncwarp();   // P rows [qr, qr+16) produced and consumed by this warp only

        // ---- O += P V : A = P rows, B = V^T rows (d) ----
#pragma unroll
        for (int kh = 0; kh < 32; kh += 8) {       // kh over n'/2
            int a0i = (qr + gr) * USTR + kh + tc;
            int a1i = a0i + 8 * USTR;
            uint32_t ah0 = uPh[a0i], ah1 = uPh[a1i], ah2 = uPh[a0i + 4], ah3 = uPh[a1i + 4];
            uint32_t al0 = uPl[a0i], al1 = uPl[a1i], al2 = uPl[a0i + 4], al3 = uPl[a1i + 4];
#pragma unroll
            for (int j = 0; j < 8; ++j) {
                int bi = (j * 8 + gr) * USTR + kh + tc;
                uint32_t bh0 = uVh[bi], bh1 = uVh[bi + 4];
                uint32_t bl0 = uVl[bi], bl1 = uVl[bi + 4];
                MMA3(oa[j], ah0,ah1,ah2,ah3, al0,al1,al2,al3, bh0,bh1, bl0,bl1);
            }
        }
    }

    // ---- epilogue: normalize, scatter to (B, S, H*HD) ----
    float i0 = 1.0f / ls0, i1 = 1.0f / ls1;
    size_t r0 = (size_t)b * (Ss * Dd) + (size_t)(s0 + qr + gr) * Dd + h * HDd;
    size_t r1 = r0 + (size_t)8 * Dd;
#pragma unroll
    for (int j = 0; j < 8; ++j) {
        *(float2*)(g_att + r0 + j * 8 + 2 * tc) = make_float2(oa[j][0] * i0, oa[j][1] * i0);
        *(float2*)(g_att + r1 + j * 8 + 2 * tc) = make_float2(oa[j][2] * i1, oa[j][3] * i1);
    }
}

// ---------------------------------------------------------------------------
// Kernel 3: layernorm over D=1024, emits bf16 hi/lo for the proj GEMM.
// Guarded cross-warp shuffle uses an 8-lane mask (full-mask here deadlocks).
// ---------------------------------------------------------------------------
__global__ __launch_bounds__(256)
void lnd_kernel(const float* __restrict__ w, const float* __restrict__ bi)
{
    __shared__ float sb2[8];
    int row = blockIdx.x;
    int tid = threadIdx.x;
    int wid = tid >> 5, lane = tid & 31;

    float4 v = *(const float4*)(g_att + (size_t)row * Dd + tid * 4);

    float s = v.x + v.y + v.z + v.w;
#pragma unroll
    for (int o = 16; o; o >>= 1) s += __shfl_xor_sync(0xffffffffu, s, o);
    if (lane == 0) sb2[wid] = s;
    __syncthreads();
    if (tid < 8) {
        float t = sb2[tid];
#pragma unroll
        for (int o = 4; o; o >>= 1) t += __shfl_xor_sync(0xFFu, t, o);
        if (tid == 0) sb2[0] = t;
    }
    __syncthreads();
    float mean = sb2[0] * (1.0f / Dd);
    __syncthreads();

    float dx = v.x - mean, dy = v.y - mean, dz = v.z - mean, dw = v.w - mean;
    float vv = dx * dx + dy * dy + dz * dz + dw * dw;
#pragma unroll
    for (int o = 16; o; o >>= 1) vv += __shfl_xor_sync(0xffffffffu, vv, o);
    if (lane == 0) sb2[wid] = vv;
    __syncthreads();
    if (tid < 8) {
        float t = sb2[tid];
#pragma unroll
        for (int o = 4; o; o >>= 1) t += __shfl_xor_sync(0xFFu, t, o);
        if (tid == 0) sb2[0] = t;
    }
    __syncthreads();
    float inv = rsqrtf(sb2[0] * (1.0f / Dd) + EPS_);

    float4 w4 = *(const float4*)(w  + tid * 4);
    float4 b4 = *(const float4*)(bi + tid * 4);
    float rx = dx * inv * w4.x + b4.x;
    float ry = dy * inv * w4.y + b4.y;
    float rz = dz * inv * w4.z + b4.z;
    float rw = dw * inv * w4.w + b4.w;

    __nv_bfloat162 h01 = __floats2bfloat162_rn(rx, ry);
    __nv_bfloat162 h23 = __floats2bfloat162_rn(rz, rw);
    float2 f01 = __bfloat1622float2(h01), f23 = __bfloat1622float2(h23);
    __nv_bfloat162 l01 = __floats2bfloat162_rn(rx - f01.x, ry - f01.y);
    __nv_bfloat162 l23 = __floats2bfloat162_rn(rz - f23.x, rw - f23.y);
    __nv_bfloat162* ph = (__nv_bfloat162*)(g_xh + (size_t)row * Dd + tid * 4);
    __nv_bfloat162* pl = (__nv_bfloat162*)(g_xl + (size_t)row * Dd + tid * 4);
    ph[0] = h01; ph[1] = h23;
    pl[0] = l01; pl[1] = l23;
}

// ---------------------------------------------------------------------------
// Kernel 4: out = xln @ proj_w^T via bf16 3-term MMAs.
// Block = 128(m) x 64(n), BK=64; operands pre-split in global bf16.
// ---------------------------------------------------------------------------
__global__ __launch_bounds__(256)
void proj_tc_kernel(float* __restrict__ out)
{
    extern __shared__ __nv_bfloat16 sb[];
    __nv_bfloat16* sXh = sb;                    // 128*72
    __nv_bfloat16* sXl = sXh + 128 * BSTR;
    __nv_bfloat16* sWh = sXl + 128 * BSTR;      // 64*72
    __nv_bfloat16* sWl = sWh + 64 * BSTR;

    const int m0 = blockIdx.y * 128;
    const int n0 = blockIdx.x * 64;
    const int tid = threadIdx.x, wid = tid >> 5, lane = tid & 31;
    const int gr = lane >> 2, tc = lane & 3;
    const int qr = wid * 16;

    const uint32_t* uXh = (const uint32_t*)sXh;
    const uint32_t* uXl = (const uint32_t*)sXl;
    const uint32_t* uWh = (const uint32_t*)sWh;
    const uint32_t* uWl = (const uint32_t*)sWl;

    float oa[8][4];
#pragma unroll
    for (int j = 0; j < 8; ++j) { oa[j][0] = oa[j][1] = oa[j][2] = oa[j][3] = 0.0f; }

    for (int kt = 0; kt < Dd; kt += 64) {
        __syncthreads();
        // fill X (128 rows x 64) and W (64 rows x 64), hi+lo, uint4 copies
#pragma unroll
        for (int i = 0; i < 4; ++i) {
            int idx = i * 256 + tid;
            int row = idx >> 3, c8 = (idx & 7) * 8;
            *(uint4*)&sXh[row * BSTR + c8] = *(const uint4*)(g_xh + (size_t)(m0 + row) * Dd + kt + c8);
            *(uint4*)&sXl[row * BSTR + c8] = *(const uint4*)(g_xl + (size_t)(m0 + row) * Dd + kt + c8);
        }
#pragma unroll
        for (int i = 0; i < 2; ++i) {
            int idx = i * 256 + tid;
            int row = idx >> 3, c8 = (idx & 7) * 8;
            *(uint4*)&sWh[row * BSTR + c8] = *(const uint4*)(g_wh + (size_t)(n0 + row) * Dd + kt + c8);
            *(uint4*)&sWl[row * BSTR + c8] = *(const uint4*)(g_wl + (size_t)(n0 + row) * Dd + kt + c8);
        }
        __syncthreads();

#pragma unroll
        for (int kh = 0; kh < 32; kh += 8) {
            int a0i = (qr + gr) * USTR + kh + tc;
            int a1i = a0i + 8 * USTR;
            uint32_t ah0 = uXh[a0i], ah1 = uXh[a1i], ah2 = uXh[a0i + 4], ah3 = uXh[a1i + 4];
            uint32_t al0 = uXl[a0i], al1 = uXl[a1i], al2 = uXl[a0i + 4], al3 = uXl[a1i + 4];
#pragma unroll
            for (int j = 0; j < 8; ++j) {
                int bi = (j * 8 + gr) * USTR + kh + tc;
                uint32_t bh0 = uWh[bi], bh1 = uWh[bi + 4];
                uint32_t bl0 = uWl[bi], bl1 = uWl[bi + 4];
                MMA3(oa[j], ah0,ah1,ah2,ah3, al0,al1,al2,al3, bh0,bh1, bl0,bl1);
            }
        }
    }

    size_t r0 = (size_t)(m0 + qr + gr) * Dd + n0;
    size_t r1 = r0 + (size_t)8 * Dd;
#pragma unroll
    for (int j = 0; j < 8; ++j) {
        *(float2*)(out + r0 + j * 8 + 2 * tc) = make_float2(oa[j][0], oa[j][1]);
        *(float2*)(out + r1 + j * 8 + 2 * tc) = make_float2(oa[j][2], oa[j][3]);
    }
}

// ---------------------------------------------------------------------------
// Launch
// Inputs: 0 x_q, 1 x_k, 2 x_v, 3 qn_w, 4 qn_b, 5 kn_w, 6 kn_b, 7 n_w, 8 n_b, 9 proj_w
// ---------------------------------------------------------------------------
extern "C" void kernel_launch(void* const* d_in, const int* in_sizes, int n_in,
                              void* d_out, int out_size)
{
    const float* xq  = (const float*)d_in[0];
    const float* xk  = (const float*)d_in[1];
    const float* xv  = (const float*)d_in[2];
    const float* qnw = (const float*)d_in[3];
    const float* qnb = (const float*)d_in[4];
    const float* knw = (const float*)d_in[5];
    const float* knb = (const float*)d_in[6];
    const float* nw  = (const float*)d_in[7];
    const float* nb  = (const float*)d_in[8];
    const float* pw  = (const float*)d_in[9];
    float* out = (float*)d_out;

    const int ATTN_SMEM = (4 * 128 * BSTR + 4 * 64 * BSTR) * 2;   // 110592 B
    const int PROJ_SMEM = (2 * 128 * BSTR + 2 * 64 * BSTR) * 2;   // 55296 B
    cudaFuncSetAttribute(attn_tc_kernel, cudaFuncAttributeMaxDynamicSharedMemorySize, ATTN_SMEM);
    cudaFuncSetAttribute(proj_tc_kernel, cudaFuncAttributeMaxDynamicSharedMemorySize, PROJ_SMEM);

    // 1) prep: K layernorm+split, V transpose+split, W split
    kln_kernel<<<(Bb * Nn) / 8, 256>>>(xk, knw, knb);
    dim3 vgrid(Nn / 64, Bb);
    vprep_kernel<<<vgrid, 256>>>(xv);
    wprep_kernel<<<(Dd * Dd / 4) / 256, 256>>>(pw);

    // 2) bf16 tensor-core flash attention : (S/128, H, B)
    dim3 agrid(Ss / 128, Hh, Bb);
    attn_tc_kernel<<<agrid, 256, ATTN_SMEM>>>(xq, qnw, qnb);

    // 3) layernorm over D (emits bf16 hi/lo)
    lnd_kernel<<<Bb * Ss, 256>>>(nw, nb);

    // 4) projection GEMM : (N/64, M/128)
    dim3 pgrid(Dd / 64, (Bb * Ss) / 128);
    proj_tc_kernel<<<pgrid, 256, PROJ_SMEM>>>(out);
}